// round 15
// baseline (speedup 1.0000x reference)
#include <cuda_runtime.h>
#include <cuda_bf16.h>
#include <cuda_fp16.h>
#include <stdint.h>
#include <math.h>

// Problem constants
#define BB 2
#define SS 1024
#define DD 512
#define HH 8
#define LL 6
#define VV 32000
#define FFN 2048
#define NT (BB*SS)          // 2048 tokens
#define MNtok (NT*DD)

// ---------------------------------------------------------------------------
// Device scratch (static, no allocations)
// ---------------------------------------------------------------------------
__device__ float g_X  [NT*DD];
__device__ float g_QKV[NT*3*DD];
__device__ float g_PART[8*NT*DD];                         // split-K partials

__device__ __nv_bfloat16 g_wqkv2[(size_t)LL*3*DD*2*DD];   // [rows, 2K] hi|lo
__device__ __nv_bfloat16 g_wo2  [(size_t)LL*DD*2*DD];
__device__ __nv_bfloat16 g_w12  [(size_t)LL*2*FFN*2*DD];  // u/g row-interleaved
__device__ __nv_bfloat16 g_w22  [(size_t)LL*DD*2*FFN];
__device__ __nv_bfloat16 g_x2   [(size_t)NT*2*DD];
__device__ __nv_bfloat16 g_att2 [(size_t)NT*2*DD];
__device__ __nv_bfloat16 g_ff2  [(size_t)NT*2*FFN];
__device__ __half        g_embh [(size_t)VV*DD];          // fp16 for LM head
__device__ __half        g_lnfh [(size_t)NT*DD];

// ---------------------------------------------------------------------------
// PTX helpers (baseline ISA only: cp.async, ldmatrix, mma.sync)
// ---------------------------------------------------------------------------
__device__ __forceinline__ uint32_t smem_to_u32(const void* p) {
    uint32_t a;
    asm("{ .reg .u64 t; cvta.to.shared.u64 t, %1; cvt.u32.u64 %0, t; }"
        : "=r"(a) : "l"(p));
    return a;
}
__device__ __forceinline__ void cp16(uint32_t dst, const void* src) {
    asm volatile("cp.async.cg.shared.global [%0], [%1], 16;\n" :: "r"(dst), "l"(src) : "memory");
}
#define CP_COMMIT()  asm volatile("cp.async.commit_group;" ::: "memory")
#define CP_WAIT1()   asm volatile("cp.async.wait_group 1;" ::: "memory")

__device__ __forceinline__ void ldm_x4(uint32_t* r, uint32_t addr) {
    asm volatile("ldmatrix.sync.aligned.m8n8.x4.shared.b16 {%0,%1,%2,%3}, [%4];"
        : "=r"(r[0]), "=r"(r[1]), "=r"(r[2]), "=r"(r[3]) : "r"(addr));
}
template<bool F16>
__device__ __forceinline__ void mma16816(float* c, const uint32_t* a,
                                         uint32_t b0, uint32_t b1) {
    if (F16)
        asm volatile(
            "mma.sync.aligned.m16n8k16.row.col.f32.f16.f16.f32 "
            "{%0,%1,%2,%3}, {%4,%5,%6,%7}, {%8,%9}, {%0,%1,%2,%3};"
            : "+f"(c[0]), "+f"(c[1]), "+f"(c[2]), "+f"(c[3])
            : "r"(a[0]), "r"(a[1]), "r"(a[2]), "r"(a[3]), "r"(b0), "r"(b1));
    else
        asm volatile(
            "mma.sync.aligned.m16n8k16.row.col.f32.bf16.bf16.f32 "
            "{%0,%1,%2,%3}, {%4,%5,%6,%7}, {%8,%9}, {%0,%1,%2,%3};"
            : "+f"(c[0]), "+f"(c[1]), "+f"(c[2]), "+f"(c[3])
            : "r"(a[0]), "r"(a[1]), "r"(a[2]), "r"(a[3]), "r"(b0), "r"(b1));
}

// smem address for (row, chunk16) with 64B pitch + XOR swizzle.
__device__ __forceinline__ uint32_t swz(int row, int chunk) {
    return (uint32_t)(row * 64 + ((chunk ^ ((row >> 1) & 3)) << 4));
}

// ---------------------------------------------------------------------------
// bf16 hi/lo split helpers
// ---------------------------------------------------------------------------
__device__ __forceinline__ void split2(float x, __nv_bfloat16* hi_p, __nv_bfloat16* lo_p) {
    __nv_bfloat16 h = __float2bfloat16_rn(x);
    *hi_p = h;
    *lo_p = __float2bfloat16_rn(x - __bfloat162float(h));
}

// Fused weight split. W1 is row-INTERLEAVED: dest row j (even) = u-row j/2,
// dest row j (odd) = g-row FFN + j/2 -> GEMM output cols (2f, 2f+1) = (u_f, g_f).
#define RQKV (LL*3*DD)
#define RWO  (LL*DD)
#define RW1  (LL*2*FFN)
#define RW2  (LL*DD)
__global__ __launch_bounds__(256) void prep_split(
    const float* __restrict__ Wqkv, const float* __restrict__ Wo,
    const float* __restrict__ W1,   const float* __restrict__ W2,
    __nv_bfloat16* __restrict__ wqkv2, __nv_bfloat16* __restrict__ wo2,
    __nv_bfloat16* __restrict__ w12,   __nv_bfloat16* __restrict__ w22)
{
    int r = blockIdx.x;
    const float* s; __nv_bfloat16* d; int K;
    if (r < RQKV)                    { s = Wqkv + (size_t)r * DD; d = wqkv2 + (size_t)r * 2 * DD; K = DD; }
    else if (r < RQKV + RWO)         { r -= RQKV; s = Wo + (size_t)r * DD; d = wo2 + (size_t)r * 2 * DD; K = DD; }
    else if (r < RQKV + RWO + RW1)   {
        r -= RQKV + RWO;
        int l = r / (2 * FFN), j = r % (2 * FFN);
        int srow = l * 2 * FFN + ((j & 1) ? FFN + (j >> 1) : (j >> 1));
        s = W1 + (size_t)srow * DD; d = w12 + (size_t)r * 2 * DD; K = DD;
    }
    else                             { r -= RQKV + RWO + RW1; s = W2 + (size_t)r * FFN; d = w22 + (size_t)r * 2 * FFN; K = FFN; }
    for (int c = threadIdx.x; c < K; c += 256)
        split2(s[c], &d[c], &d[K + c]);
}

// fp32 -> fp16 plain convert
__global__ __launch_bounds__(256) void cvt_half_kernel(
    const float* __restrict__ s, __half* __restrict__ d, int n)
{
    int i = (blockIdx.x * 256 + threadIdx.x) * 4;
    if (i < n) {
        float4 v = *(const float4*)(s + i);
        d[i + 0] = __float2half_rn(v.x);
        d[i + 1] = __float2half_rn(v.y);
        d[i + 2] = __float2half_rn(v.z);
        d[i + 3] = __float2half_rn(v.w);
    }
}

// ---------------------------------------------------------------------------
// Tensor-core GEMM with optional split-K (blockIdx.z = split index).
// EPI=0: C = A*B^T (+bias / ->PART). EPI=1: fused SwiGLU epilogue -> ff2.
// GX=1: blockIdx.x maps to M (co-resident blocks share the B tile -> L2 reuse;
//       used for the LM head where B = 32MB embedding).
// ---------------------------------------------------------------------------
template<int TM, int TN, int PASSES, int MINB, int EPI, int GX>
__global__ __launch_bounds__(256, MINB)
void gemm_mma(const __nv_bfloat16* __restrict__ A2,
              const __nv_bfloat16* __restrict__ B2,
              const float* __restrict__ bias,
              float* __restrict__ C, int N, int K, int Ks, size_t partStride)
{
    constexpr bool F16 = (PASSES == 1);
    constexpr int WM = TM / 2, WN = TN / 4;
    constexpr int MI = WM / 16;
    constexpr int NI = WN / 8;
    constexpr int NB = WN / 16;
    constexpr int AT = (PASSES == 3) ? 2 : 1;
    constexpr int SA = AT * TM * 64;
    constexpr int SB = AT * TN * 64;
    constexpr int STAGE = SA + SB;
    constexpr int ACH = AT * TM * 4;
    constexpr int NCH = ACH + AT * TN * 4;

    extern __shared__ __align__(128) char dsm[];
    uint32_t sbase = smem_to_u32(dsm);

    int tid = threadIdx.x, lane = tid & 31, warp = tid >> 5;
    int wm = warp >> 2, wn = warp & 3;
    size_t bm = (size_t)(GX ? blockIdx.x : blockIdx.y) * TM;
    size_t bn = (size_t)(GX ? blockIdx.y : blockIdx.x) * TN;
    int kOff = blockIdx.z * Ks;
    C += (size_t)blockIdx.z * partStride;
    int astr = (PASSES == 3) ? 2 * K : K;
    int nk = Ks / 32;

    float acc[MI][NI][4];
    #pragma unroll
    for (int mi = 0; mi < MI; mi++)
        #pragma unroll
        for (int ni = 0; ni < NI; ni++)
            #pragma unroll
            for (int j = 0; j < 4; j++) acc[mi][ni][j] = 0.f;

    auto load_stage = [&](int it) {
        int buf = it % 3;
        int kc = kOff + it * 32;
        uint32_t sAp = sbase + buf * STAGE;
        uint32_t sBp = sAp + SA;
        #pragma unroll
        for (int ii = 0; ii < NCH / 256; ii++) {
            int i = tid + ii * 256;
            if (i < ACH) {
                int row, half, seg;
                if (PASSES == 3) { row = i >> 3; half = (i >> 2) & 1; seg = i & 3; }
                else             { row = i >> 2; half = 0;            seg = i & 3; }
                cp16(sAp + (uint32_t)(half * (TM * 64)) + swz(row, seg),
                     A2 + (bm + row) * (size_t)astr + half * K + kc + seg * 8);
            } else {
                int j = i - ACH;
                int row, half, seg;
                if (PASSES == 3) { row = j >> 3; half = (j >> 2) & 1; seg = j & 3; }
                else             { row = j >> 2; half = 0;            seg = j & 3; }
                cp16(sBp + (uint32_t)(half * (TN * 64)) + swz(row, seg),
                     B2 + (bn + row) * (size_t)astr + half * K + kc + seg * 8);
            }
        }
    };

    load_stage(0); CP_COMMIT();
    if (nk > 1) load_stage(1);
    CP_COMMIT();

    for (int it = 0; it < nk; it++) {
        CP_WAIT1();
        __syncthreads();
        if (it + 2 < nk) load_stage(it + 2);
        CP_COMMIT();

        int buf = it % 3;
        uint32_t sAhi = sbase + buf * STAGE;
        uint32_t sAlo = sAhi + TM * 64;
        uint32_t sBhi = sAhi + SA;
        uint32_t sBlo = sBhi + TN * 64;

        #pragma unroll
        for (int ks = 0; ks < 2; ks++) {
            int arow = wm * WM + (lane & 15);
            int achk = ks * 2 + (lane >> 4);
            uint32_t aoff = swz(arow, achk);
            int sel = lane >> 3, within = lane & 7;
            int nrow = wn * WN + within + ((sel >> 1) << 3);
            int bchk = ks * 2 + (sel & 1);
            uint32_t boff = swz(nrow, bchk);

            uint32_t ahf[MI][4], bhf[NB][4];
            #pragma unroll
            for (int mi = 0; mi < MI; mi++)
                ldm_x4(ahf[mi], sAhi + aoff + mi * 16 * 64);
            #pragma unroll
            for (int n2 = 0; n2 < NB; n2++)
                ldm_x4(bhf[n2], sBhi + boff + n2 * 16 * 64);

            // pass 0: hi * hi
            #pragma unroll
            for (int mi = 0; mi < MI; mi++)
                #pragma unroll
                for (int ni = 0; ni < NI; ni++)
                    mma16816<F16>(acc[mi][ni], ahf[mi],
                                  bhf[ni >> 1][(ni & 1) * 2],
                                  bhf[ni >> 1][(ni & 1) * 2 + 1]);
            if (PASSES == 3) {
                uint32_t blf[NB][4];
                #pragma unroll
                for (int n2 = 0; n2 < NB; n2++)
                    ldm_x4(blf[n2], sBlo + boff + n2 * 16 * 64);
                // pass 1: Ahi * Blo
                #pragma unroll
                for (int mi = 0; mi < MI; mi++)
                    #pragma unroll
                    for (int ni = 0; ni < NI; ni++)
                        mma16816<F16>(acc[mi][ni], ahf[mi],
                                      blf[ni >> 1][(ni & 1) * 2],
                                      blf[ni >> 1][(ni & 1) * 2 + 1]);
                uint32_t alf[MI][4];
                #pragma unroll
                for (int mi = 0; mi < MI; mi++)
                    ldm_x4(alf[mi], sAlo + aoff + mi * 16 * 64);
                // pass 2: Alo * Bhi
                #pragma unroll
                for (int mi = 0; mi < MI; mi++)
                    #pragma unroll
                    for (int ni = 0; ni < NI; ni++)
                        mma16816<F16>(acc[mi][ni], alf[mi],
                                      bhf[ni >> 1][(ni & 1) * 2],
                                      bhf[ni >> 1][(ni & 1) * 2 + 1]);
            }
        }
    }

    // epilogue
    int r0 = (int)bm + wm * WM + (lane >> 2);
    int c0 = (int)bn + wn * WN + (lane & 3) * 2;
    if (EPI == 1) {
        // SwiGLU fusion: cols (c, c+1) = (u_f, g_f), f = c/2.
        __nv_bfloat16* F = (__nv_bfloat16*)C;
        #pragma unroll
        for (int mi = 0; mi < MI; mi++) {
            #pragma unroll
            for (int ni = 0; ni < NI; ni++) {
                int row = r0 + mi * 16;
                int col = c0 + ni * 8;
                int f = col >> 1;
                float bu = bias[f], bg = bias[FFN + f];
                #pragma unroll
                for (int hrow = 0; hrow < 2; hrow++) {
                    int rr = row + hrow * 8;
                    float u = acc[mi][ni][hrow * 2 + 0] + bu;
                    float g = acc[mi][ni][hrow * 2 + 1] + bg;
                    float v = u * g / (1.0f + __expf(-g));
                    split2(v, &F[(size_t)rr * (2 * FFN) + f],
                              &F[(size_t)rr * (2 * FFN) + FFN + f]);
                }
            }
        }
    } else {
        #pragma unroll
        for (int mi = 0; mi < MI; mi++) {
            #pragma unroll
            for (int ni = 0; ni < NI; ni++) {
                int row = r0 + mi * 16;
                int col = c0 + ni * 8;
                float bx = 0.f, by = 0.f;
                if (bias) { bx = bias[col]; by = bias[col + 1]; }
                float2 lo, hi;
                lo.x = acc[mi][ni][0] + bx; lo.y = acc[mi][ni][1] + by;
                hi.x = acc[mi][ni][2] + bx; hi.y = acc[mi][ni][3] + by;
                *(float2*)(C + (size_t)row * N + col) = lo;
                *(float2*)(C + (size_t)(row + 8) * N + col) = hi;
            }
        }
    }
}

// ---------------------------------------------------------------------------
// Embedding + positional encoding -> X fp32 and X2 bf16 split
// ---------------------------------------------------------------------------
__global__ __launch_bounds__(128) void embed_kernel(
    const int* __restrict__ ids, const float* __restrict__ emb,
    float* __restrict__ x, __nv_bfloat16* __restrict__ x2)
{
    int n = blockIdx.x;
    int s = n & (SS - 1);
    int id = ids[n];
    const float Cc = -0.01798894591761708f;  // -ln(10000)/512
    #pragma unroll
    for (int k = 0; k < 4; k++) {
        int d = threadIdx.x + k * 128;
        float ang = (float)s * expf((float)(d & ~1) * Cc);
        float pe = (d & 1) ? cosf(ang) : sinf(ang);
        float v = emb[(size_t)id * DD + d] + pe;
        x[(size_t)n * DD + d] = v;
        split2(v, &x2[(size_t)n * 2 * DD + d], &x2[(size_t)n * 2 * DD + DD + d]);
    }
}

// ---------------------------------------------------------------------------
// Windowed attention: 4 queries/block, warp-per-query.
// Score: 4 keys/iter. Softmax exp via __expf (MUFU). V pass: float4 prob
// loads (sc rows 16B-aligned), 4 independent accumulators.
// ---------------------------------------------------------------------------
__global__ __launch_bounds__(128) void attn_kernel(
    const float* __restrict__ qkv, __nv_bfloat16* __restrict__ out2)
{
    int s0 = blockIdx.x * 4, h = blockIdx.y, b = blockIdx.z;
    int win = (h + 1) * 64;
    int tid = threadIdx.x, lane = tid & 31, warp = tid >> 5;

    __shared__ __align__(16) float sc[4][512];

    const float* base = qkv + (size_t)b * SS * (3 * DD);

    int sq = s0 + warp;
    int j0 = sq - win + 1; if (j0 < 0) j0 = 0;
    int cnt = sq + 1 - j0;

    int g = lane >> 3;             // key subgroup 0..3
    int l8 = lane & 7;             // dim octet within key
    const float4* qp = (const float4*)(base + (size_t)sq * (3 * DD) + h * 64 + l8 * 8);
    float4 qa = qp[0], qb = qp[1];

    float m = -3.4e38f;
    for (int i0 = 0; i0 < cnt; i0 += 4) {       // uniform across the warp
        int i = i0 + g;
        int ic = i < cnt ? i : cnt - 1;         // clamp overshoot subgroups
        const float4* kp = (const float4*)(base + (size_t)(j0 + ic) * (3 * DD) + DD + h * 64 + l8 * 8);
        float4 k0 = kp[0], k1 = kp[1];
        float d = fmaf(k0.x, qa.x, fmaf(k0.y, qa.y, fmaf(k0.z, qa.z, k0.w * qa.w)));
        d = fmaf(k1.x, qb.x, fmaf(k1.y, qb.y, fmaf(k1.z, qb.z, fmaf(k1.w, qb.w, d))));
        d += __shfl_xor_sync(0xffffffffu, d, 1);
        d += __shfl_xor_sync(0xffffffffu, d, 2);
        d += __shfl_xor_sync(0xffffffffu, d, 4);
        d *= 0.125f;                              // 1/sqrt(64)
        if (i < cnt) {
            if (l8 == 0) sc[warp][i] = d;
            m = fmaxf(m, d);
        }
    }
    m = fmaxf(m, __shfl_xor_sync(0xffffffffu, m, 8));
    m = fmaxf(m, __shfl_xor_sync(0xffffffffu, m, 16));
    __syncwarp();

    float ssum = 0.f;
    for (int i = lane; i < cnt; i += 32) {
        float e = __expf(sc[warp][i] - m);
        sc[warp][i] = e;
        ssum += e;
    }
    #pragma unroll
    for (int o = 16; o; o >>= 1) ssum += __shfl_xor_sync(0xffffffffu, ssum, o);
    float inv = 1.0f / ssum;
    __syncwarp();

    // V pass: lane owns dims {2*lane, 2*lane+1}, 4 independent accs
    const float* vb = base + (size_t)j0 * (3 * DD) + 2 * DD + h * 64 + lane * 2;
    float2 a0 = {0,0}, a1 = {0,0}, a2 = {0,0}, a3 = {0,0};
    int i = 0;
    for (; i + 4 <= cnt; i += 4) {
        float4 p = *(const float4*)&sc[warp][i];
        float2 v0 = *(const float2*)(vb + (size_t)(i + 0) * (3 * DD));
        float2 v1 = *(const float2*)(vb + (size_t)(i + 1) * (3 * DD));
        float2 v2 = *(const float2*)(vb + (size_t)(i + 2) * (3 * DD));
        float2 v3 = *(const float2*)(vb + (size_t)(i + 3) * (3 * DD));
        a0.x = fmaf(p.x, v0.x, a0.x); a0.y = fmaf(p.x, v0.y, a0.y);
        a1.x = fmaf(p.y, v1.x, a1.x); a1.y = fmaf(p.y, v1.y, a1.y);
        a2.x = fmaf(p.z, v2.x, a2.x); a2.y = fmaf(p.z, v2.y, a2.y);
        a3.x = fmaf(p.w, v3.x, a3.x); a3.y = fmaf(p.w, v3.y, a3.y);
    }
    for (; i < cnt; i++) {
        float p = sc[warp][i];
        float2 v = *(const float2*)(vb + (size_t)i * (3 * DD));
        a0.x = fmaf(p, v.x, a0.x); a0.y = fmaf(p, v.y, a0.y);
    }
    float rx = (a0.x + a1.x) + (a2.x + a3.x);
    float ry = (a0.y + a1.y) + (a2.y + a3.y);

    size_t n = (size_t)(b * SS + sq);
    __nv_bfloat16* oh = out2 + n * 2 * DD + h * 64 + lane * 2;
    __nv_bfloat16* ol = oh + DD;
    split2(rx * inv, &oh[0], &ol[0]);
    split2(ry * inv, &oh[1], &ol[1]);
}

// ---------------------------------------------------------------------------
// (residual + split-K partial sum + bias) + LayerNorm.
// ---------------------------------------------------------------------------
template<int S>
__global__ __launch_bounds__(128) void ln_kernel(
    const float* __restrict__ xin, const float* __restrict__ part,
    const float* __restrict__ pbias,
    const float* __restrict__ g, const float* __restrict__ b,
    float* __restrict__ out, __nv_bfloat16* __restrict__ out2,
    __half* __restrict__ outh)
{
    int row = blockIdx.x;
    const float* xr = xin + (size_t)row * DD;
    int tid = threadIdx.x;
    float v[4];
    float s = 0.f, s2 = 0.f;
    #pragma unroll
    for (int k = 0; k < 4; k++) {
        int d = tid + k * 128;
        float t = xr[d];
        if (S > 0) {
            float r = pbias[d];
            #pragma unroll
            for (int ss = 0; ss < S; ss++)
                r += part[(size_t)ss * MNtok + (size_t)row * DD + d];
            t += r;
        }
        v[k] = t; s += t; s2 += t * t;
    }
    __shared__ float sh[2][4];
    #pragma unroll
    for (int o = 16; o; o >>= 1) {
        s  += __shfl_xor_sync(0xffffffffu, s, o);
        s2 += __shfl_xor_sync(0xffffffffu, s2, o);
    }
    if ((tid & 31) == 0) { sh[0][tid >> 5] = s; sh[1][tid >> 5] = s2; }
    __syncthreads();
    s  = sh[0][0] + sh[0][1] + sh[0][2] + sh[0][3];
    s2 = sh[1][0] + sh[1][1] + sh[1][2] + sh[1][3];
    float mean = s * (1.0f / 512.0f);
    float var = s2 * (1.0f / 512.0f) - mean * mean;
    float rstd = rsqrtf(var + 1e-5f);
    #pragma unroll
    for (int k = 0; k < 4; k++) {
        int d = tid + k * 128;
        float o = (v[k] - mean) * rstd * g[d] + b[d];
        if (out) out[(size_t)row * DD + d] = o;
        if (out2) split2(o, &out2[(size_t)row * 2 * DD + d],
                            &out2[(size_t)row * 2 * DD + DD + d]);
        if (outh) outh[(size_t)row * DD + d] = __float2half_rn(o);
    }
}

// ---------------------------------------------------------------------------
// Launch
// ---------------------------------------------------------------------------
#define SMEM_64_128_3  (3 * (2*64*64 + 2*128*64))    // 73728
#define SMEM_128_128_3 (3 * (2*128*64 + 2*128*64))   // 98304
#define SMEM_LM128     (3 * (128*64 + 128*64))       // 49152

extern "C" void kernel_launch(void* const* d_in, const int* in_sizes, int n_in,
                              void* d_out, int out_size)
{
    const int*   ids   = (const int*)  d_in[0];
    const float* emb   = (const float*)d_in[1];
    const float* Wqkv  = (const float*)d_in[2];
    const float* bqkv  = (const float*)d_in[3];
    const float* Wo    = (const float*)d_in[4];
    const float* bo    = (const float*)d_in[5];
    const float* W1    = (const float*)d_in[6];
    const float* b1    = (const float*)d_in[7];
    const float* W2    = (const float*)d_in[8];
    const float* b2    = (const float*)d_in[9];
    const float* ln1_g = (const float*)d_in[10];
    const float* ln1_b = (const float*)d_in[11];
    const float* ln2_g = (const float*)d_in[12];
    const float* ln2_b = (const float*)d_in[13];
    const float* lnf_g = (const float*)d_in[14];
    const float* lnf_b = (const float*)d_in[15];
    float* out = (float*)d_out;

    float *X, *QKV, *PART;
    __nv_bfloat16 *wqkv2, *wo2, *w12, *w22, *x2, *att2, *ff2;
    __half *embh, *lnfh;
    cudaGetSymbolAddress((void**)&X,    g_X);
    cudaGetSymbolAddress((void**)&QKV,  g_QKV);
    cudaGetSymbolAddress((void**)&PART, g_PART);
    cudaGetSymbolAddress((void**)&wqkv2,g_wqkv2);
    cudaGetSymbolAddress((void**)&wo2,  g_wo2);
    cudaGetSymbolAddress((void**)&w12,  g_w12);
    cudaGetSymbolAddress((void**)&w22,  g_w22);
    cudaGetSymbolAddress((void**)&x2,   g_x2);
    cudaGetSymbolAddress((void**)&att2, g_att2);
    cudaGetSymbolAddress((void**)&ff2,  g_ff2);
    cudaGetSymbolAddress((void**)&embh, g_embh);
    cudaGetSymbolAddress((void**)&lnfh, g_lnfh);

    cudaFuncSetAttribute((const void*)gemm_mma<64,128,3,3,0,0>,
                         cudaFuncAttributeMaxDynamicSharedMemorySize, SMEM_64_128_3);
    cudaFuncSetAttribute((const void*)gemm_mma<128,128,3,2,1,0>,
                         cudaFuncAttributeMaxDynamicSharedMemorySize, SMEM_128_128_3);
    cudaFuncSetAttribute((const void*)gemm_mma<128,128,1,2,0,1>,
                         cudaFuncAttributeMaxDynamicSharedMemorySize, SMEM_LM128);

    // weight preprocessing (graph-replayed each call)
    prep_split<<<RQKV + RWO + RW1 + RW2, 256>>>(Wqkv, Wo, W1, W2,
                                                wqkv2, wo2, w12, w22);
    cvt_half_kernel<<<(VV * DD) / 1024, 256>>>(emb, embh, VV * DD);

    embed_kernel<<<NT, 128>>>(ids, emb, X, x2);

    const int MN = NT * DD;
    for (int l = 0; l < LL; l++) {
        // QKV: [2048,512] x [1536,512]^T   (64x128, 384 blocks, 3 CTA/SM)
        gemm_mma<64,128,3,3,0,0><<<dim3(12, 32), 256, SMEM_64_128_3>>>(
            x2, wqkv2 + (size_t)l * 3 * DD * 2 * DD,
            bqkv + (size_t)l * 3 * DD, QKV, 3 * DD, DD, DD, 0);
        // windowed attention -> att2 (bf16 split)
        attn_kernel<<<dim3(SS / 4, HH, BB), 128>>>(QKV, att2);
        // Wo: [2048,512] x [512,512]^T   split-K=2 -> 256 blocks
        gemm_mma<64,128,3,3,0,0><<<dim3(4, 32, 2), 256, SMEM_64_128_3>>>(
            att2, wo2 + (size_t)l * DD * 2 * DD,
            nullptr, PART, DD, DD, DD / 2, (size_t)MN);
        // x = LN(x + sum(partials) + bo)
        ln_kernel<2><<<NT, 128>>>(X, PART, bo + (size_t)l * DD,
                                  ln1_g + (size_t)l * DD, ln1_b + (size_t)l * DD,
                                  X, x2, nullptr);
        // W1 + fused SwiGLU: [2048,512] x [4096,512]^T -> ff2 bf16 split
        gemm_mma<128,128,3,2,1,0><<<dim3(32, 16), 256, SMEM_128_128_3>>>(
            x2, w12 + (size_t)l * 2 * FFN * 2 * DD,
            b1 + (size_t)l * 2 * FFN, (float*)ff2, 2 * FFN, DD, DD, 0);
        // W2: [2048,2048] x [512,2048]^T  split-K=8 -> 1024 blocks
        gemm_mma<64,128,3,3,0,0><<<dim3(4, 32, 8), 256, SMEM_64_128_3>>>(
            ff2, w22 + (size_t)l * DD * 2 * FFN,
            nullptr, PART, DD, FFN, FFN / 8, (size_t)MN);
        // x = LN(x + sum(partials) + b2)
        ln_kernel<8><<<NT, 128>>>(X, PART, b2 + (size_t)l * DD,
                                  ln2_g + (size_t)l * DD, ln2_b + (size_t)l * DD,
                                  X, x2, nullptr);
    }

    // final LN -> fp16, tied LM head (fp16, 128x128, GX=1: M fastest so
    // co-resident blocks share the embedding B tile)
    ln_kernel<0><<<NT, 128>>>(X, nullptr, nullptr, lnf_g, lnf_b,
                              nullptr, nullptr, lnfh);
    gemm_mma<128,128,1,2,0,1><<<dim3(NT / 128, VV / 128), 256, SMEM_LM128>>>(
        (const __nv_bfloat16*)lnfh, (const __nv_bfloat16*)embh,
        nullptr, out, VV, DD, DD, 0);
}

// round 16
// speedup vs baseline: 1.1803x; 1.1803x over previous
#include <cuda_runtime.h>
#include <cuda_bf16.h>
#include <cuda_fp16.h>
#include <stdint.h>
#include <math.h>

// Problem constants
#define BB 2
#define SS 1024
#define DD 512
#define HH 8
#define LL 6
#define VV 32000
#define FFN 2048
#define NT (BB*SS)          // 2048 tokens
#define MNtok (NT*DD)

// ---------------------------------------------------------------------------
// Device scratch (static, no allocations)
// ---------------------------------------------------------------------------
__device__ float g_X  [NT*DD];
__device__ float g_QKV[NT*3*DD];
__device__ float g_PART[8*NT*DD];                      // split-K partials

__device__ __half g_wqkvh[(size_t)LL*3*DD*DD];         // plain fp16 weights
__device__ __half g_woh  [(size_t)LL*DD*DD];
__device__ __half g_w1h  [(size_t)LL*2*FFN*DD];        // u/g row-interleaved
__device__ __half g_w2h  [(size_t)LL*DD*FFN];
__device__ __half g_x2   [(size_t)NT*2*DD];            // activations hi|lo
__device__ __half g_att2 [(size_t)NT*2*DD];
__device__ __half g_ff2  [(size_t)NT*2*FFN];
__device__ __half g_embh [(size_t)VV*DD];              // fp16 for LM head
__device__ __half g_lnfh [(size_t)NT*DD];

// ---------------------------------------------------------------------------
// PTX helpers (baseline ISA only: cp.async, ldmatrix, mma.sync)
// ---------------------------------------------------------------------------
__device__ __forceinline__ uint32_t smem_to_u32(const void* p) {
    uint32_t a;
    asm("{ .reg .u64 t; cvta.to.shared.u64 t, %1; cvt.u32.u64 %0, t; }"
        : "=r"(a) : "l"(p));
    return a;
}
__device__ __forceinline__ void cp16(uint32_t dst, const void* src) {
    asm volatile("cp.async.cg.shared.global [%0], [%1], 16;\n" :: "r"(dst), "l"(src) : "memory");
}
#define CP_COMMIT()  asm volatile("cp.async.commit_group;" ::: "memory")
#define CP_WAIT1()   asm volatile("cp.async.wait_group 1;" ::: "memory")

__device__ __forceinline__ void ldm_x4(uint32_t* r, uint32_t addr) {
    asm volatile("ldmatrix.sync.aligned.m8n8.x4.shared.b16 {%0,%1,%2,%3}, [%4];"
        : "=r"(r[0]), "=r"(r[1]), "=r"(r[2]), "=r"(r[3]) : "r"(addr));
}
__device__ __forceinline__ void mma16816h(float* c, const uint32_t* a,
                                          uint32_t b0, uint32_t b1) {
    asm volatile(
        "mma.sync.aligned.m16n8k16.row.col.f32.f16.f16.f32 "
        "{%0,%1,%2,%3}, {%4,%5,%6,%7}, {%8,%9}, {%0,%1,%2,%3};"
        : "+f"(c[0]), "+f"(c[1]), "+f"(c[2]), "+f"(c[3])
        : "r"(a[0]), "r"(a[1]), "r"(a[2]), "r"(a[3]), "r"(b0), "r"(b1));
}

// smem address for (row, chunk16) with 64B pitch + XOR swizzle.
__device__ __forceinline__ uint32_t swz(int row, int chunk) {
    return (uint32_t)(row * 64 + ((chunk ^ ((row >> 1) & 3)) << 4));
}

// ---------------------------------------------------------------------------
// fp16 hi/lo split helper (activations)
// ---------------------------------------------------------------------------
__device__ __forceinline__ void split2h(float x, __half* hi_p, __half* lo_p) {
    __half h = __float2half_rn(x);
    *hi_p = h;
    *lo_p = __float2half_rn(x - __half2float(h));
}

// Fused weight convert (plain fp16). W1 row-INTERLEAVED: dest row j even =
// u-row j/2, odd = g-row FFN + j/2 -> GEMM cols (2f,2f+1) = (u_f, g_f).
#define RQKV (LL*3*DD)
#define RWO  (LL*DD)
#define RW1  (LL*2*FFN)
#define RW2  (LL*DD)
__global__ __launch_bounds__(256) void prep_w(
    const float* __restrict__ Wqkv, const float* __restrict__ Wo,
    const float* __restrict__ W1,   const float* __restrict__ W2,
    __half* __restrict__ wqkvh, __half* __restrict__ woh,
    __half* __restrict__ w1h,   __half* __restrict__ w2h)
{
    int r = blockIdx.x;
    const float* s; __half* d; int K;
    if (r < RQKV)                    { s = Wqkv + (size_t)r * DD; d = wqkvh + (size_t)r * DD; K = DD; }
    else if (r < RQKV + RWO)         { r -= RQKV; s = Wo + (size_t)r * DD; d = woh + (size_t)r * DD; K = DD; }
    else if (r < RQKV + RWO + RW1)   {
        r -= RQKV + RWO;
        int l = r / (2 * FFN), j = r % (2 * FFN);
        int srow = l * 2 * FFN + ((j & 1) ? FFN + (j >> 1) : (j >> 1));
        s = W1 + (size_t)srow * DD; d = w1h + (size_t)r * DD; K = DD;
    }
    else                             { r -= RQKV + RWO + RW1; s = W2 + (size_t)r * FFN; d = w2h + (size_t)r * FFN; K = FFN; }
    for (int c = threadIdx.x; c < K; c += 256)
        d[c] = __float2half_rn(s[c]);
}

// fp32 -> fp16 plain convert (embedding for LM head)
__global__ __launch_bounds__(256) void cvt_half_kernel(
    const float* __restrict__ s, __half* __restrict__ d, int n)
{
    int i = (blockIdx.x * 256 + threadIdx.x) * 4;
    if (i < n) {
        float4 v = *(const float4*)(s + i);
        d[i + 0] = __float2half_rn(v.x);
        d[i + 1] = __float2half_rn(v.y);
        d[i + 2] = __float2half_rn(v.z);
        d[i + 3] = __float2half_rn(v.w);
    }
}

// ---------------------------------------------------------------------------
// fp16 tensor-core GEMM with optional split-K (blockIdx.z = split index).
// PASSES=2: A = [rows, 2K] fp16 hi|lo (activations), B = [rows, K] fp16.
//           C = Ahi*B^T + Alo*B^T  (error ~2^-12, dropped A*Wlo term).
// PASSES=1: A,B = [rows, K] fp16, single pass (LM head).
// EPI=1: fused SwiGLU epilogue -> ff2 fp16 hi|lo.
// GX=1: blockIdx.x -> M (B-tile L2 reuse for the LM head).
// ---------------------------------------------------------------------------
template<int TM, int TN, int PASSES, int MINB, int EPI, int GX>
__global__ __launch_bounds__(256, MINB)
void gemm_mma(const __half* __restrict__ A2,
              const __half* __restrict__ B2,
              const float* __restrict__ bias,
              float* __restrict__ C, int N, int K, int Ks, size_t partStride)
{
    constexpr int WM = TM / 2, WN = TN / 4;
    constexpr int MI = WM / 16;
    constexpr int NI = WN / 8;
    constexpr int NB = WN / 16;
    constexpr int ATA = (PASSES == 2) ? 2 : 1;
    constexpr int SA = ATA * TM * 64;
    constexpr int SB = TN * 64;
    constexpr int STAGE = SA + SB;
    constexpr int ACH = ATA * TM * 4;
    constexpr int NCH = ACH + TN * 4;

    extern __shared__ __align__(128) char dsm[];
    uint32_t sbase = smem_to_u32(dsm);

    int tid = threadIdx.x, lane = tid & 31, warp = tid >> 5;
    int wm = warp >> 2, wn = warp & 3;
    size_t bm = (size_t)(GX ? blockIdx.x : blockIdx.y) * TM;
    size_t bn = (size_t)(GX ? blockIdx.y : blockIdx.x) * TN;
    int kOff = blockIdx.z * Ks;
    C += (size_t)blockIdx.z * partStride;
    int astr = ATA * K;
    int nk = Ks / 32;

    float acc[MI][NI][4];
    #pragma unroll
    for (int mi = 0; mi < MI; mi++)
        #pragma unroll
        for (int ni = 0; ni < NI; ni++)
            #pragma unroll
            for (int j = 0; j < 4; j++) acc[mi][ni][j] = 0.f;

    auto load_stage = [&](int it) {
        int buf = it % 3;
        int kc = kOff + it * 32;
        uint32_t sAp = sbase + buf * STAGE;
        uint32_t sBp = sAp + SA;
        #pragma unroll
        for (int ii = 0; ii < NCH / 256; ii++) {
            int i = tid + ii * 256;
            if (i < ACH) {
                int row, half, seg;
                if (PASSES == 2) { row = i >> 3; half = (i >> 2) & 1; seg = i & 3; }
                else             { row = i >> 2; half = 0;            seg = i & 3; }
                cp16(sAp + (uint32_t)(half * (TM * 64)) + swz(row, seg),
                     A2 + (bm + row) * (size_t)astr + half * K + kc + seg * 8);
            } else {
                int j = i - ACH;
                int row = j >> 2, seg = j & 3;
                cp16(sBp + swz(row, seg),
                     B2 + (bn + row) * (size_t)K + kc + seg * 8);
            }
        }
    };

    load_stage(0); CP_COMMIT();
    if (nk > 1) load_stage(1);
    CP_COMMIT();

    for (int it = 0; it < nk; it++) {
        CP_WAIT1();
        __syncthreads();
        if (it + 2 < nk) load_stage(it + 2);
        CP_COMMIT();

        int buf = it % 3;
        uint32_t sAhi = sbase + buf * STAGE;
        uint32_t sAlo = sAhi + TM * 64;
        uint32_t sB   = sAhi + SA;

        #pragma unroll
        for (int ks = 0; ks < 2; ks++) {
            int arow = wm * WM + (lane & 15);
            int achk = ks * 2 + (lane >> 4);
            uint32_t aoff = swz(arow, achk);
            int sel = lane >> 3, within = lane & 7;
            int nrow = wn * WN + within + ((sel >> 1) << 3);
            int bchk = ks * 2 + (sel & 1);
            uint32_t boff = swz(nrow, bchk);

            uint32_t ahf[MI][4], bhf[NB][4];
            #pragma unroll
            for (int mi = 0; mi < MI; mi++)
                ldm_x4(ahf[mi], sAhi + aoff + mi * 16 * 64);
            #pragma unroll
            for (int n2 = 0; n2 < NB; n2++)
                ldm_x4(bhf[n2], sB + boff + n2 * 16 * 64);

            // pass 0: Ahi * B
            #pragma unroll
            for (int mi = 0; mi < MI; mi++)
                #pragma unroll
                for (int ni = 0; ni < NI; ni++)
                    mma16816h(acc[mi][ni], ahf[mi],
                              bhf[ni >> 1][(ni & 1) * 2],
                              bhf[ni >> 1][(ni & 1) * 2 + 1]);
            if (PASSES == 2) {
                uint32_t alf[MI][4];
                #pragma unroll
                for (int mi = 0; mi < MI; mi++)
                    ldm_x4(alf[mi], sAlo + aoff + mi * 16 * 64);
                // pass 1: Alo * B
                #pragma unroll
                for (int mi = 0; mi < MI; mi++)
                    #pragma unroll
                    for (int ni = 0; ni < NI; ni++)
                        mma16816h(acc[mi][ni], alf[mi],
                                  bhf[ni >> 1][(ni & 1) * 2],
                                  bhf[ni >> 1][(ni & 1) * 2 + 1]);
            }
        }
    }

    // epilogue
    int r0 = (int)bm + wm * WM + (lane >> 2);
    int c0 = (int)bn + wn * WN + (lane & 3) * 2;
    if (EPI == 1) {
        // SwiGLU fusion: cols (c, c+1) = (u_f, g_f), f = c/2 -> ff2 hi|lo.
        __half* F = (__half*)C;
        #pragma unroll
        for (int mi = 0; mi < MI; mi++) {
            #pragma unroll
            for (int ni = 0; ni < NI; ni++) {
                int row = r0 + mi * 16;
                int col = c0 + ni * 8;
                int f = col >> 1;
                float bu = bias[f], bg = bias[FFN + f];
                #pragma unroll
                for (int hrow = 0; hrow < 2; hrow++) {
                    int rr = row + hrow * 8;
                    float u = acc[mi][ni][hrow * 2 + 0] + bu;
                    float g = acc[mi][ni][hrow * 2 + 1] + bg;
                    float v = u * g / (1.0f + __expf(-g));
                    split2h(v, &F[(size_t)rr * (2 * FFN) + f],
                               &F[(size_t)rr * (2 * FFN) + FFN + f]);
                }
            }
        }
    } else {
        #pragma unroll
        for (int mi = 0; mi < MI; mi++) {
            #pragma unroll
            for (int ni = 0; ni < NI; ni++) {
                int row = r0 + mi * 16;
                int col = c0 + ni * 8;
                float bx = 0.f, by = 0.f;
                if (bias) { bx = bias[col]; by = bias[col + 1]; }
                float2 lo, hi;
                lo.x = acc[mi][ni][0] + bx; lo.y = acc[mi][ni][1] + by;
                hi.x = acc[mi][ni][2] + bx; hi.y = acc[mi][ni][3] + by;
                *(float2*)(C + (size_t)row * N + col) = lo;
                *(float2*)(C + (size_t)(row + 8) * N + col) = hi;
            }
        }
    }
}

// ---------------------------------------------------------------------------
// Embedding + positional encoding -> X fp32 and X2 fp16 split
// ---------------------------------------------------------------------------
__global__ __launch_bounds__(128) void embed_kernel(
    const int* __restrict__ ids, const float* __restrict__ emb,
    float* __restrict__ x, __half* __restrict__ x2)
{
    int n = blockIdx.x;
    int s = n & (SS - 1);
    int id = ids[n];
    const float Cc = -0.01798894591761708f;  // -ln(10000)/512
    #pragma unroll
    for (int k = 0; k < 4; k++) {
        int d = threadIdx.x + k * 128;
        float ang = (float)s * expf((float)(d & ~1) * Cc);
        float pe = (d & 1) ? cosf(ang) : sinf(ang);
        float v = emb[(size_t)id * DD + d] + pe;
        x[(size_t)n * DD + d] = v;
        split2h(v, &x2[(size_t)n * 2 * DD + d], &x2[(size_t)n * 2 * DD + DD + d]);
    }
}

// ---------------------------------------------------------------------------
// Windowed attention: 4 queries/block, warp-per-query (verified R12 core).
// Output: fp16 hi/lo split.
// ---------------------------------------------------------------------------
__global__ __launch_bounds__(128) void attn_kernel(
    const float* __restrict__ qkv, __half* __restrict__ out2)
{
    int s0 = blockIdx.x * 4, h = blockIdx.y, b = blockIdx.z;
    int win = (h + 1) * 64;
    int tid = threadIdx.x, lane = tid & 31, warp = tid >> 5;

    __shared__ __align__(16) float sc[4][512];

    const float* base = qkv + (size_t)b * SS * (3 * DD);

    int sq = s0 + warp;
    int j0 = sq - win + 1; if (j0 < 0) j0 = 0;
    int cnt = sq + 1 - j0;

    int g = lane >> 3;             // key subgroup 0..3
    int l8 = lane & 7;             // dim octet within key
    const float4* qp = (const float4*)(base + (size_t)sq * (3 * DD) + h * 64 + l8 * 8);
    float4 qa = qp[0], qb = qp[1];

    float m = -3.4e38f;
    for (int i0 = 0; i0 < cnt; i0 += 4) {       // uniform across the warp
        int i = i0 + g;
        int ic = i < cnt ? i : cnt - 1;
        const float4* kp = (const float4*)(base + (size_t)(j0 + ic) * (3 * DD) + DD + h * 64 + l8 * 8);
        float4 k0 = kp[0], k1 = kp[1];
        float d = fmaf(k0.x, qa.x, fmaf(k0.y, qa.y, fmaf(k0.z, qa.z, k0.w * qa.w)));
        d = fmaf(k1.x, qb.x, fmaf(k1.y, qb.y, fmaf(k1.z, qb.z, fmaf(k1.w, qb.w, d))));
        d += __shfl_xor_sync(0xffffffffu, d, 1);
        d += __shfl_xor_sync(0xffffffffu, d, 2);
        d += __shfl_xor_sync(0xffffffffu, d, 4);
        d *= 0.125f;                              // 1/sqrt(64)
        if (i < cnt) {
            if (l8 == 0) sc[warp][i] = d;
            m = fmaxf(m, d);
        }
    }
    m = fmaxf(m, __shfl_xor_sync(0xffffffffu, m, 8));
    m = fmaxf(m, __shfl_xor_sync(0xffffffffu, m, 16));
    __syncwarp();

    float ssum = 0.f;
    for (int i = lane; i < cnt; i += 32) {
        float e = __expf(sc[warp][i] - m);
        sc[warp][i] = e;
        ssum += e;
    }
    #pragma unroll
    for (int o = 16; o; o >>= 1) ssum += __shfl_xor_sync(0xffffffffu, ssum, o);
    float inv = 1.0f / ssum;
    __syncwarp();

    // V pass: lane owns dims {2*lane, 2*lane+1}, 4 independent accs
    const float* vb = base + (size_t)j0 * (3 * DD) + 2 * DD + h * 64 + lane * 2;
    float2 a0 = {0,0}, a1 = {0,0}, a2 = {0,0}, a3 = {0,0};
    int i = 0;
    for (; i + 4 <= cnt; i += 4) {
        float4 p = *(const float4*)&sc[warp][i];
        float2 v0 = *(const float2*)(vb + (size_t)(i + 0) * (3 * DD));
        float2 v1 = *(const float2*)(vb + (size_t)(i + 1) * (3 * DD));
        float2 v2 = *(const float2*)(vb + (size_t)(i + 2) * (3 * DD));
        float2 v3 = *(const float2*)(vb + (size_t)(i + 3) * (3 * DD));
        a0.x = fmaf(p.x, v0.x, a0.x); a0.y = fmaf(p.x, v0.y, a0.y);
        a1.x = fmaf(p.y, v1.x, a1.x); a1.y = fmaf(p.y, v1.y, a1.y);
        a2.x = fmaf(p.z, v2.x, a2.x); a2.y = fmaf(p.z, v2.y, a2.y);
        a3.x = fmaf(p.w, v3.x, a3.x); a3.y = fmaf(p.w, v3.y, a3.y);
    }
    for (; i < cnt; i++) {
        float p = sc[warp][i];
        float2 v = *(const float2*)(vb + (size_t)i * (3 * DD));
        a0.x = fmaf(p, v.x, a0.x); a0.y = fmaf(p, v.y, a0.y);
    }
    float rx = (a0.x + a1.x) + (a2.x + a3.x);
    float ry = (a0.y + a1.y) + (a2.y + a3.y);

    size_t n = (size_t)(b * SS + sq);
    __half* oh = out2 + n * 2 * DD + h * 64 + lane * 2;
    __half* ol = oh + DD;
    split2h(rx * inv, &oh[0], &ol[0]);
    split2h(ry * inv, &oh[1], &ol[1]);
}

// ---------------------------------------------------------------------------
// (residual + split-K partial sum + bias) + LayerNorm.
// out2 = fp16 hi/lo split; outh = fp16 plain (LM head input).
// ---------------------------------------------------------------------------
template<int S>
__global__ __launch_bounds__(128) void ln_kernel(
    const float* __restrict__ xin, const float* __restrict__ part,
    const float* __restrict__ pbias,
    const float* __restrict__ g, const float* __restrict__ b,
    float* __restrict__ out, __half* __restrict__ out2,
    __half* __restrict__ outh)
{
    int row = blockIdx.x;
    const float* xr = xin + (size_t)row * DD;
    int tid = threadIdx.x;
    float v[4];
    float s = 0.f, s2 = 0.f;
    #pragma unroll
    for (int k = 0; k < 4; k++) {
        int d = tid + k * 128;
        float t = xr[d];
        if (S > 0) {
            float r = pbias[d];
            #pragma unroll
            for (int ss = 0; ss < S; ss++)
                r += part[(size_t)ss * MNtok + (size_t)row * DD + d];
            t += r;
        }
        v[k] = t; s += t; s2 += t * t;
    }
    __shared__ float sh[2][4];
    #pragma unroll
    for (int o = 16; o; o >>= 1) {
        s  += __shfl_xor_sync(0xffffffffu, s, o);
        s2 += __shfl_xor_sync(0xffffffffu, s2, o);
    }
    if ((tid & 31) == 0) { sh[0][tid >> 5] = s; sh[1][tid >> 5] = s2; }
    __syncthreads();
    s  = sh[0][0] + sh[0][1] + sh[0][2] + sh[0][3];
    s2 = sh[1][0] + sh[1][1] + sh[1][2] + sh[1][3];
    float mean = s * (1.0f / 512.0f);
    float var = s2 * (1.0f / 512.0f) - mean * mean;
    float rstd = rsqrtf(var + 1e-5f);
    #pragma unroll
    for (int k = 0; k < 4; k++) {
        int d = tid + k * 128;
        float o = (v[k] - mean) * rstd * g[d] + b[d];
        if (out) out[(size_t)row * DD + d] = o;
        if (out2) split2h(o, &out2[(size_t)row * 2 * DD + d],
                             &out2[(size_t)row * 2 * DD + DD + d]);
        if (outh) outh[(size_t)row * DD + d] = __float2half_rn(o);
    }
}

// ---------------------------------------------------------------------------
// Launch
// ---------------------------------------------------------------------------
#define SMEM_64_128_2 (3 * (2*64*64 + 128*64))    // 49152
#define SMEM_LM128    (3 * (128*64 + 128*64))     // 49152

extern "C" void kernel_launch(void* const* d_in, const int* in_sizes, int n_in,
                              void* d_out, int out_size)
{
    const int*   ids   = (const int*)  d_in[0];
    const float* emb   = (const float*)d_in[1];
    const float* Wqkv  = (const float*)d_in[2];
    const float* bqkv  = (const float*)d_in[3];
    const float* Wo    = (const float*)d_in[4];
    const float* bo    = (const float*)d_in[5];
    const float* W1    = (const float*)d_in[6];
    const float* b1    = (const float*)d_in[7];
    const float* W2    = (const float*)d_in[8];
    const float* b2    = (const float*)d_in[9];
    const float* ln1_g = (const float*)d_in[10];
    const float* ln1_b = (const float*)d_in[11];
    const float* ln2_g = (const float*)d_in[12];
    const float* ln2_b = (const float*)d_in[13];
    const float* lnf_g = (const float*)d_in[14];
    const float* lnf_b = (const float*)d_in[15];
    float* out = (float*)d_out;

    float *X, *QKV, *PART;
    __half *wqkvh, *woh, *w1h, *w2h, *x2, *att2, *ff2, *embh, *lnfh;
    cudaGetSymbolAddress((void**)&X,    g_X);
    cudaGetSymbolAddress((void**)&QKV,  g_QKV);
    cudaGetSymbolAddress((void**)&PART, g_PART);
    cudaGetSymbolAddress((void**)&wqkvh,g_wqkvh);
    cudaGetSymbolAddress((void**)&woh,  g_woh);
    cudaGetSymbolAddress((void**)&w1h,  g_w1h);
    cudaGetSymbolAddress((void**)&w2h,  g_w2h);
    cudaGetSymbolAddress((void**)&x2,   g_x2);
    cudaGetSymbolAddress((void**)&att2, g_att2);
    cudaGetSymbolAddress((void**)&ff2,  g_ff2);
    cudaGetSymbolAddress((void**)&embh, g_embh);
    cudaGetSymbolAddress((void**)&lnfh, g_lnfh);

    cudaFuncSetAttribute((const void*)gemm_mma<64,128,2,3,0,0>,
                         cudaFuncAttributeMaxDynamicSharedMemorySize, SMEM_64_128_2);
    cudaFuncSetAttribute((const void*)gemm_mma<64,128,2,3,1,0>,
                         cudaFuncAttributeMaxDynamicSharedMemorySize, SMEM_64_128_2);
    cudaFuncSetAttribute((const void*)gemm_mma<128,128,1,2,0,1>,
                         cudaFuncAttributeMaxDynamicSharedMemorySize, SMEM_LM128);

    // weight preprocessing (graph-replayed each call)
    prep_w<<<RQKV + RWO + RW1 + RW2, 256>>>(Wqkv, Wo, W1, W2,
                                            wqkvh, woh, w1h, w2h);
    cvt_half_kernel<<<(VV * DD) / 1024, 256>>>(emb, embh, VV * DD);

    embed_kernel<<<NT, 128>>>(ids, emb, X, x2);

    const int MN = NT * DD;
    for (int l = 0; l < LL; l++) {
        // QKV: [2048,512] x [1536,512]^T   (64x128, 384 blocks, 3 CTA/SM)
        gemm_mma<64,128,2,3,0,0><<<dim3(12, 32), 256, SMEM_64_128_2>>>(
            x2, wqkvh + (size_t)l * 3 * DD * DD,
            bqkv + (size_t)l * 3 * DD, QKV, 3 * DD, DD, DD, 0);
        // windowed attention -> att2 (fp16 split)
        attn_kernel<<<dim3(SS / 4, HH, BB), 128>>>(QKV, att2);
        // Wo: [2048,512] x [512,512]^T   split-K=2 -> 256 blocks
        gemm_mma<64,128,2,3,0,0><<<dim3(4, 32, 2), 256, SMEM_64_128_2>>>(
            att2, woh + (size_t)l * DD * DD,
            nullptr, PART, DD, DD, DD / 2, (size_t)MN);
        // x = LN(x + sum(partials) + bo)
        ln_kernel<2><<<NT, 128>>>(X, PART, bo + (size_t)l * DD,
                                  ln1_g + (size_t)l * DD, ln1_b + (size_t)l * DD,
                                  X, x2, nullptr);
        // W1 + fused SwiGLU: [2048,512] x [4096,512]^T -> ff2 fp16 split
        gemm_mma<64,128,2,3,1,0><<<dim3(32, 32), 256, SMEM_64_128_2>>>(
            x2, w1h + (size_t)l * 2 * FFN * DD,
            b1 + (size_t)l * 2 * FFN, (float*)ff2, 2 * FFN, DD, DD, 0);
        // W2: [2048,2048] x [512,2048]^T  split-K=8 -> 1024 blocks
        gemm_mma<64,128,2,3,0,0><<<dim3(4, 32, 8), 256, SMEM_64_128_2>>>(
            ff2, w2h + (size_t)l * DD * FFN,
            nullptr, PART, DD, FFN, FFN / 8, (size_t)MN);
        // x = LN(x + sum(partials) + b2)
        ln_kernel<8><<<NT, 128>>>(X, PART, b2 + (size_t)l * DD,
                                  ln2_g + (size_t)l * DD, ln2_b + (size_t)l * DD,
                                  X, x2, nullptr);
    }

    // final LN -> fp16, tied LM head (fp16 single-pass, 128x128, GX=1)
    ln_kernel<0><<<NT, 128>>>(X, nullptr, nullptr, lnf_g, lnf_b,
                              nullptr, nullptr, lnfh);
    gemm_mma<128,128,1,2,0,1><<<dim3(NT / 128, VV / 128), 256, SMEM_LM128>>>(
        lnfh, embh, nullptr, out, VV, DD, DD, 0);
}

// round 17
// speedup vs baseline: 1.3938x; 1.1809x over previous
#include <cuda_runtime.h>
#include <cuda_bf16.h>
#include <cuda_fp16.h>
#include <stdint.h>
#include <math.h>

// Problem constants
#define BB 2
#define SS 1024
#define DD 512
#define HH 8
#define LL 6
#define VV 32000
#define FFN 2048
#define NT (BB*SS)          // 2048 tokens
#define MNtok (NT*DD)

// ---------------------------------------------------------------------------
// Device scratch (static, no allocations)
// ---------------------------------------------------------------------------
__device__ float g_X  [NT*DD];
__device__ float g_QKV[NT*3*DD];
__device__ float g_PART[8*NT*DD];                      // split-K partials

__device__ __half g_wqkvh[(size_t)LL*3*DD*DD];         // plain fp16 weights
__device__ __half g_woh  [(size_t)LL*DD*DD];
__device__ __half g_w1h  [(size_t)LL*2*FFN*DD];        // u/g row-interleaved
__device__ __half g_w2h  [(size_t)LL*DD*FFN];
__device__ __half g_x2   [(size_t)NT*DD];              // plain fp16 activations
__device__ __half g_att2 [(size_t)NT*DD];
__device__ __half g_ff2  [(size_t)NT*FFN];
__device__ __half g_embh [(size_t)VV*DD];              // fp16 for LM head
__device__ __half g_lnfh [(size_t)NT*DD];

// ---------------------------------------------------------------------------
// PTX helpers (baseline ISA only: cp.async, ldmatrix, mma.sync)
// ---------------------------------------------------------------------------
__device__ __forceinline__ uint32_t smem_to_u32(const void* p) {
    uint32_t a;
    asm("{ .reg .u64 t; cvta.to.shared.u64 t, %1; cvt.u32.u64 %0, t; }"
        : "=r"(a) : "l"(p));
    return a;
}
__device__ __forceinline__ void cp16(uint32_t dst, const void* src) {
    asm volatile("cp.async.cg.shared.global [%0], [%1], 16;\n" :: "r"(dst), "l"(src) : "memory");
}
#define CP_COMMIT()  asm volatile("cp.async.commit_group;" ::: "memory")
#define CP_WAIT1()   asm volatile("cp.async.wait_group 1;" ::: "memory")

__device__ __forceinline__ void ldm_x4(uint32_t* r, uint32_t addr) {
    asm volatile("ldmatrix.sync.aligned.m8n8.x4.shared.b16 {%0,%1,%2,%3}, [%4];"
        : "=r"(r[0]), "=r"(r[1]), "=r"(r[2]), "=r"(r[3]) : "r"(addr));
}
__device__ __forceinline__ void mma16816h(float* c, const uint32_t* a,
                                          uint32_t b0, uint32_t b1) {
    asm volatile(
        "mma.sync.aligned.m16n8k16.row.col.f32.f16.f16.f32 "
        "{%0,%1,%2,%3}, {%4,%5,%6,%7}, {%8,%9}, {%0,%1,%2,%3};"
        : "+f"(c[0]), "+f"(c[1]), "+f"(c[2]), "+f"(c[3])
        : "r"(a[0]), "r"(a[1]), "r"(a[2]), "r"(a[3]), "r"(b0), "r"(b1));
}

// smem address for (row, chunk16) with 64B pitch + XOR swizzle.
__device__ __forceinline__ uint32_t swz(int row, int chunk) {
    return (uint32_t)(row * 64 + ((chunk ^ ((row >> 1) & 3)) << 4));
}

// Fused weight convert (plain fp16). W1 row-INTERLEAVED: dest row j even =
// u-row j/2, odd = g-row FFN + j/2 -> GEMM cols (2f,2f+1) = (u_f, g_f).
#define RQKV (LL*3*DD)
#define RWO  (LL*DD)
#define RW1  (LL*2*FFN)
#define RW2  (LL*DD)
__global__ __launch_bounds__(256) void prep_w(
    const float* __restrict__ Wqkv, const float* __restrict__ Wo,
    const float* __restrict__ W1,   const float* __restrict__ W2,
    __half* __restrict__ wqkvh, __half* __restrict__ woh,
    __half* __restrict__ w1h,   __half* __restrict__ w2h)
{
    int r = blockIdx.x;
    const float* s; __half* d; int K;
    if (r < RQKV)                    { s = Wqkv + (size_t)r * DD; d = wqkvh + (size_t)r * DD; K = DD; }
    else if (r < RQKV + RWO)         { r -= RQKV; s = Wo + (size_t)r * DD; d = woh + (size_t)r * DD; K = DD; }
    else if (r < RQKV + RWO + RW1)   {
        r -= RQKV + RWO;
        int l = r / (2 * FFN), j = r % (2 * FFN);
        int srow = l * 2 * FFN + ((j & 1) ? FFN + (j >> 1) : (j >> 1));
        s = W1 + (size_t)srow * DD; d = w1h + (size_t)r * DD; K = DD;
    }
    else                             { r -= RQKV + RWO + RW1; s = W2 + (size_t)r * FFN; d = w2h + (size_t)r * FFN; K = FFN; }
    for (int c = threadIdx.x; c < K; c += 256)
        d[c] = __float2half_rn(s[c]);
}

// fp32 -> fp16 plain convert (embedding for LM head)
__global__ __launch_bounds__(256) void cvt_half_kernel(
    const float* __restrict__ s, __half* __restrict__ d, int n)
{
    int i = (blockIdx.x * 256 + threadIdx.x) * 4;
    if (i < n) {
        float4 v = *(const float4*)(s + i);
        d[i + 0] = __float2half_rn(v.x);
        d[i + 1] = __float2half_rn(v.y);
        d[i + 2] = __float2half_rn(v.z);
        d[i + 3] = __float2half_rn(v.w);
    }
}

// ---------------------------------------------------------------------------
// fp16 tensor-core GEMM with optional split-K (blockIdx.z = split index).
// A,B = [rows, K] fp16 plain, single pass, fp32 accumulate.
// EPI=1: fused SwiGLU epilogue -> ff2 fp16 plain.
// GX=1: blockIdx.x -> M (B-tile L2 reuse for the LM head).
// ---------------------------------------------------------------------------
template<int TM, int TN, int MINB, int EPI, int GX>
__global__ __launch_bounds__(256, MINB)
void gemm_mma(const __half* __restrict__ A2,
              const __half* __restrict__ B2,
              const float* __restrict__ bias,
              float* __restrict__ C, int N, int K, int Ks, size_t partStride)
{
    constexpr int WM = TM / 2, WN = TN / 4;
    constexpr int MI = WM / 16;
    constexpr int NI = WN / 8;
    constexpr int NB = WN / 16;
    constexpr int SA = TM * 64;
    constexpr int SB = TN * 64;
    constexpr int STAGE = SA + SB;
    constexpr int ACH = TM * 4;
    constexpr int NCH = ACH + TN * 4;

    extern __shared__ __align__(128) char dsm[];
    uint32_t sbase = smem_to_u32(dsm);

    int tid = threadIdx.x, lane = tid & 31, warp = tid >> 5;
    int wm = warp >> 2, wn = warp & 3;
    size_t bm = (size_t)(GX ? blockIdx.x : blockIdx.y) * TM;
    size_t bn = (size_t)(GX ? blockIdx.y : blockIdx.x) * TN;
    int kOff = blockIdx.z * Ks;
    C += (size_t)blockIdx.z * partStride;
    int nk = Ks / 32;

    float acc[MI][NI][4];
    #pragma unroll
    for (int mi = 0; mi < MI; mi++)
        #pragma unroll
        for (int ni = 0; ni < NI; ni++)
            #pragma unroll
            for (int j = 0; j < 4; j++) acc[mi][ni][j] = 0.f;

    auto load_stage = [&](int it) {
        int buf = it % 3;
        int kc = kOff + it * 32;
        uint32_t sAp = sbase + buf * STAGE;
        uint32_t sBp = sAp + SA;
        #pragma unroll
        for (int ii = 0; ii < NCH / 256; ii++) {
            int i = tid + ii * 256;
            if (i < ACH) {
                int row = i >> 2, seg = i & 3;
                cp16(sAp + swz(row, seg),
                     A2 + (bm + row) * (size_t)K + kc + seg * 8);
            } else {
                int j = i - ACH;
                int row = j >> 2, seg = j & 3;
                cp16(sBp + swz(row, seg),
                     B2 + (bn + row) * (size_t)K + kc + seg * 8);
            }
        }
    };

    load_stage(0); CP_COMMIT();
    if (nk > 1) load_stage(1);
    CP_COMMIT();

    for (int it = 0; it < nk; it++) {
        CP_WAIT1();
        __syncthreads();
        if (it + 2 < nk) load_stage(it + 2);
        CP_COMMIT();

        int buf = it % 3;
        uint32_t sA = sbase + buf * STAGE;
        uint32_t sB = sA + SA;

        #pragma unroll
        for (int ks = 0; ks < 2; ks++) {
            int arow = wm * WM + (lane & 15);
            int achk = ks * 2 + (lane >> 4);
            uint32_t aoff = swz(arow, achk);
            int sel = lane >> 3, within = lane & 7;
            int nrow = wn * WN + within + ((sel >> 1) << 3);
            int bchk = ks * 2 + (sel & 1);
            uint32_t boff = swz(nrow, bchk);

            uint32_t ahf[MI][4], bhf[NB][4];
            #pragma unroll
            for (int mi = 0; mi < MI; mi++)
                ldm_x4(ahf[mi], sA + aoff + mi * 16 * 64);
            #pragma unroll
            for (int n2 = 0; n2 < NB; n2++)
                ldm_x4(bhf[n2], sB + boff + n2 * 16 * 64);

            #pragma unroll
            for (int mi = 0; mi < MI; mi++)
                #pragma unroll
                for (int ni = 0; ni < NI; ni++)
                    mma16816h(acc[mi][ni], ahf[mi],
                              bhf[ni >> 1][(ni & 1) * 2],
                              bhf[ni >> 1][(ni & 1) * 2 + 1]);
        }
    }

    // epilogue
    int r0 = (int)bm + wm * WM + (lane >> 2);
    int c0 = (int)bn + wn * WN + (lane & 3) * 2;
    if (EPI == 1) {
        // SwiGLU fusion: cols (c, c+1) = (u_f, g_f), f = c/2 -> ff2 fp16.
        __half* F = (__half*)C;
        #pragma unroll
        for (int mi = 0; mi < MI; mi++) {
            #pragma unroll
            for (int ni = 0; ni < NI; ni++) {
                int row = r0 + mi * 16;
                int col = c0 + ni * 8;
                int f = col >> 1;
                float bu = bias[f], bg = bias[FFN + f];
                #pragma unroll
                for (int hrow = 0; hrow < 2; hrow++) {
                    int rr = row + hrow * 8;
                    float u = acc[mi][ni][hrow * 2 + 0] + bu;
                    float g = acc[mi][ni][hrow * 2 + 1] + bg;
                    float v = u * g / (1.0f + __expf(-g));
                    F[(size_t)rr * FFN + f] = __float2half_rn(v);
                }
            }
        }
    } else {
        #pragma unroll
        for (int mi = 0; mi < MI; mi++) {
            #pragma unroll
            for (int ni = 0; ni < NI; ni++) {
                int row = r0 + mi * 16;
                int col = c0 + ni * 8;
                float bx = 0.f, by = 0.f;
                if (bias) { bx = bias[col]; by = bias[col + 1]; }
                float2 lo, hi;
                lo.x = acc[mi][ni][0] + bx; lo.y = acc[mi][ni][1] + by;
                hi.x = acc[mi][ni][2] + bx; hi.y = acc[mi][ni][3] + by;
                *(float2*)(C + (size_t)row * N + col) = lo;
                *(float2*)(C + (size_t)(row + 8) * N + col) = hi;
            }
        }
    }
}

// ---------------------------------------------------------------------------
// Embedding + positional encoding -> X fp32 and x2 fp16
// ---------------------------------------------------------------------------
__global__ __launch_bounds__(128) void embed_kernel(
    const int* __restrict__ ids, const float* __restrict__ emb,
    float* __restrict__ x, __half* __restrict__ x2)
{
    int n = blockIdx.x;
    int s = n & (SS - 1);
    int id = ids[n];
    const float Cc = -0.01798894591761708f;  // -ln(10000)/512
    #pragma unroll
    for (int k = 0; k < 4; k++) {
        int d = threadIdx.x + k * 128;
        float ang = (float)s * expf((float)(d & ~1) * Cc);
        float pe = (d & 1) ? cosf(ang) : sinf(ang);
        float v = emb[(size_t)id * DD + d] + pe;
        x[(size_t)n * DD + d] = v;
        x2[(size_t)n * DD + d] = __float2half_rn(v);
    }
}

// ---------------------------------------------------------------------------
// Windowed attention: 4 queries/block, warp-per-query (verified R12 core).
// Output: plain fp16.
// ---------------------------------------------------------------------------
__global__ __launch_bounds__(128) void attn_kernel(
    const float* __restrict__ qkv, __half* __restrict__ out2)
{
    int s0 = blockIdx.x * 4, h = blockIdx.y, b = blockIdx.z;
    int win = (h + 1) * 64;
    int tid = threadIdx.x, lane = tid & 31, warp = tid >> 5;

    __shared__ __align__(16) float sc[4][512];

    const float* base = qkv + (size_t)b * SS * (3 * DD);

    int sq = s0 + warp;
    int j0 = sq - win + 1; if (j0 < 0) j0 = 0;
    int cnt = sq + 1 - j0;

    int g = lane >> 3;             // key subgroup 0..3
    int l8 = lane & 7;             // dim octet within key
    const float4* qp = (const float4*)(base + (size_t)sq * (3 * DD) + h * 64 + l8 * 8);
    float4 qa = qp[0], qb = qp[1];

    float m = -3.4e38f;
    for (int i0 = 0; i0 < cnt; i0 += 4) {       // uniform across the warp
        int i = i0 + g;
        int ic = i < cnt ? i : cnt - 1;
        const float4* kp = (const float4*)(base + (size_t)(j0 + ic) * (3 * DD) + DD + h * 64 + l8 * 8);
        float4 k0 = kp[0], k1 = kp[1];
        float d = fmaf(k0.x, qa.x, fmaf(k0.y, qa.y, fmaf(k0.z, qa.z, k0.w * qa.w)));
        d = fmaf(k1.x, qb.x, fmaf(k1.y, qb.y, fmaf(k1.z, qb.z, fmaf(k1.w, qb.w, d))));
        d += __shfl_xor_sync(0xffffffffu, d, 1);
        d += __shfl_xor_sync(0xffffffffu, d, 2);
        d += __shfl_xor_sync(0xffffffffu, d, 4);
        d *= 0.125f;                              // 1/sqrt(64)
        if (i < cnt) {
            if (l8 == 0) sc[warp][i] = d;
            m = fmaxf(m, d);
        }
    }
    m = fmaxf(m, __shfl_xor_sync(0xffffffffu, m, 8));
    m = fmaxf(m, __shfl_xor_sync(0xffffffffu, m, 16));
    __syncwarp();

    float ssum = 0.f;
    for (int i = lane; i < cnt; i += 32) {
        float e = __expf(sc[warp][i] - m);
        sc[warp][i] = e;
        ssum += e;
    }
    #pragma unroll
    for (int o = 16; o; o >>= 1) ssum += __shfl_xor_sync(0xffffffffu, ssum, o);
    float inv = 1.0f / ssum;
    __syncwarp();

    // V pass: lane owns dims {2*lane, 2*lane+1}, 4 independent accs
    const float* vb = base + (size_t)j0 * (3 * DD) + 2 * DD + h * 64 + lane * 2;
    float2 a0 = {0,0}, a1 = {0,0}, a2 = {0,0}, a3 = {0,0};
    int i = 0;
    for (; i + 4 <= cnt; i += 4) {
        float4 p = *(const float4*)&sc[warp][i];
        float2 v0 = *(const float2*)(vb + (size_t)(i + 0) * (3 * DD));
        float2 v1 = *(const float2*)(vb + (size_t)(i + 1) * (3 * DD));
        float2 v2 = *(const float2*)(vb + (size_t)(i + 2) * (3 * DD));
        float2 v3 = *(const float2*)(vb + (size_t)(i + 3) * (3 * DD));
        a0.x = fmaf(p.x, v0.x, a0.x); a0.y = fmaf(p.x, v0.y, a0.y);
        a1.x = fmaf(p.y, v1.x, a1.x); a1.y = fmaf(p.y, v1.y, a1.y);
        a2.x = fmaf(p.z, v2.x, a2.x); a2.y = fmaf(p.z, v2.y, a2.y);
        a3.x = fmaf(p.w, v3.x, a3.x); a3.y = fmaf(p.w, v3.y, a3.y);
    }
    for (; i < cnt; i++) {
        float p = sc[warp][i];
        float2 v = *(const float2*)(vb + (size_t)i * (3 * DD));
        a0.x = fmaf(p, v.x, a0.x); a0.y = fmaf(p, v.y, a0.y);
    }
    float rx = (a0.x + a1.x) + (a2.x + a3.x);
    float ry = (a0.y + a1.y) + (a2.y + a3.y);

    size_t n = (size_t)(b * SS + sq);
    __half* oh = out2 + n * DD + h * 64 + lane * 2;
    oh[0] = __float2half_rn(rx * inv);
    oh[1] = __float2half_rn(ry * inv);
}

// ---------------------------------------------------------------------------
// (residual + split-K partial sum + bias) + LayerNorm.
// outh = plain fp16 output (next GEMM's A operand).
// ---------------------------------------------------------------------------
template<int S>
__global__ __launch_bounds__(128) void ln_kernel(
    const float* __restrict__ xin, const float* __restrict__ part,
    const float* __restrict__ pbias,
    const float* __restrict__ g, const float* __restrict__ b,
    float* __restrict__ out, __half* __restrict__ outh)
{
    int row = blockIdx.x;
    const float* xr = xin + (size_t)row * DD;
    int tid = threadIdx.x;
    float v[4];
    float s = 0.f, s2 = 0.f;
    #pragma unroll
    for (int k = 0; k < 4; k++) {
        int d = tid + k * 128;
        float t = xr[d];
        if (S > 0) {
            float r = pbias[d];
            #pragma unroll
            for (int ss = 0; ss < S; ss++)
                r += part[(size_t)ss * MNtok + (size_t)row * DD + d];
            t += r;
        }
        v[k] = t; s += t; s2 += t * t;
    }
    __shared__ float sh[2][4];
    #pragma unroll
    for (int o = 16; o; o >>= 1) {
        s  += __shfl_xor_sync(0xffffffffu, s, o);
        s2 += __shfl_xor_sync(0xffffffffu, s2, o);
    }
    if ((tid & 31) == 0) { sh[0][tid >> 5] = s; sh[1][tid >> 5] = s2; }
    __syncthreads();
    s  = sh[0][0] + sh[0][1] + sh[0][2] + sh[0][3];
    s2 = sh[1][0] + sh[1][1] + sh[1][2] + sh[1][3];
    float mean = s * (1.0f / 512.0f);
    float var = s2 * (1.0f / 512.0f) - mean * mean;
    float rstd = rsqrtf(var + 1e-5f);
    #pragma unroll
    for (int k = 0; k < 4; k++) {
        int d = tid + k * 128;
        float o = (v[k] - mean) * rstd * g[d] + b[d];
        if (out) out[(size_t)row * DD + d] = o;
        if (outh) outh[(size_t)row * DD + d] = __float2half_rn(o);
    }
}

// ---------------------------------------------------------------------------
// Launch
// ---------------------------------------------------------------------------
#define SMEM_64_128 (3 * (64*64 + 128*64))     // 36864
#define SMEM_LM128  (3 * (128*64 + 128*64))    // 49152

extern "C" void kernel_launch(void* const* d_in, const int* in_sizes, int n_in,
                              void* d_out, int out_size)
{
    const int*   ids   = (const int*)  d_in[0];
    const float* emb   = (const float*)d_in[1];
    const float* Wqkv  = (const float*)d_in[2];
    const float* bqkv  = (const float*)d_in[3];
    const float* Wo    = (const float*)d_in[4];
    const float* bo    = (const float*)d_in[5];
    const float* W1    = (const float*)d_in[6];
    const float* b1    = (const float*)d_in[7];
    const float* W2    = (const float*)d_in[8];
    const float* b2    = (const float*)d_in[9];
    const float* ln1_g = (const float*)d_in[10];
    const float* ln1_b = (const float*)d_in[11];
    const float* ln2_g = (const float*)d_in[12];
    const float* ln2_b = (const float*)d_in[13];
    const float* lnf_g = (const float*)d_in[14];
    const float* lnf_b = (const float*)d_in[15];
    float* out = (float*)d_out;

    float *X, *QKV, *PART;
    __half *wqkvh, *woh, *w1h, *w2h, *x2, *att2, *ff2, *embh, *lnfh;
    cudaGetSymbolAddress((void**)&X,    g_X);
    cudaGetSymbolAddress((void**)&QKV,  g_QKV);
    cudaGetSymbolAddress((void**)&PART, g_PART);
    cudaGetSymbolAddress((void**)&wqkvh,g_wqkvh);
    cudaGetSymbolAddress((void**)&woh,  g_woh);
    cudaGetSymbolAddress((void**)&w1h,  g_w1h);
    cudaGetSymbolAddress((void**)&w2h,  g_w2h);
    cudaGetSymbolAddress((void**)&x2,   g_x2);
    cudaGetSymbolAddress((void**)&att2, g_att2);
    cudaGetSymbolAddress((void**)&ff2,  g_ff2);
    cudaGetSymbolAddress((void**)&embh, g_embh);
    cudaGetSymbolAddress((void**)&lnfh, g_lnfh);

    cudaFuncSetAttribute((const void*)gemm_mma<64,128,3,0,0>,
                         cudaFuncAttributeMaxDynamicSharedMemorySize, SMEM_64_128);
    cudaFuncSetAttribute((const void*)gemm_mma<64,128,3,1,0>,
                         cudaFuncAttributeMaxDynamicSharedMemorySize, SMEM_64_128);
    cudaFuncSetAttribute((const void*)gemm_mma<128,128,2,0,1>,
                         cudaFuncAttributeMaxDynamicSharedMemorySize, SMEM_LM128);

    // weight preprocessing (graph-replayed each call)
    prep_w<<<RQKV + RWO + RW1 + RW2, 256>>>(Wqkv, Wo, W1, W2,
                                            wqkvh, woh, w1h, w2h);
    cvt_half_kernel<<<(VV * DD) / 1024, 256>>>(emb, embh, VV * DD);

    embed_kernel<<<NT, 128>>>(ids, emb, X, x2);

    const int MN = NT * DD;
    for (int l = 0; l < LL; l++) {
        // QKV: [2048,512] x [1536,512]^T   (64x128, 384 blocks, 3 CTA/SM)
        gemm_mma<64,128,3,0,0><<<dim3(12, 32), 256, SMEM_64_128>>>(
            x2, wqkvh + (size_t)l * 3 * DD * DD,
            bqkv + (size_t)l * 3 * DD, QKV, 3 * DD, DD, DD, 0);
        // windowed attention -> att2 (fp16)
        attn_kernel<<<dim3(SS / 4, HH, BB), 128>>>(QKV, att2);
        // Wo: [2048,512] x [512,512]^T   split-K=2 -> 256 blocks
        gemm_mma<64,128,3,0,0><<<dim3(4, 32, 2), 256, SMEM_64_128>>>(
            att2, woh + (size_t)l * DD * DD,
            nullptr, PART, DD, DD, DD / 2, (size_t)MN);
        // x = LN(x + sum(partials) + bo)
        ln_kernel<2><<<NT, 128>>>(X, PART, bo + (size_t)l * DD,
                                  ln1_g + (size_t)l * DD, ln1_b + (size_t)l * DD,
                                  X, x2);
        // W1 + fused SwiGLU: [2048,512] x [4096,512]^T -> ff2 fp16
        gemm_mma<64,128,3,1,0><<<dim3(32, 32), 256, SMEM_64_128>>>(
            x2, w1h + (size_t)l * 2 * FFN * DD,
            b1 + (size_t)l * 2 * FFN, (float*)ff2, 2 * FFN, DD, DD, 0);
        // W2: [2048,2048] x [512,2048]^T  split-K=8 -> 1024 blocks
        gemm_mma<64,128,3,0,0><<<dim3(4, 32, 8), 256, SMEM_64_128>>>(
            ff2, w2h + (size_t)l * DD * FFN,
            nullptr, PART, DD, FFN, FFN / 8, (size_t)MN);
        // x = LN(x + sum(partials) + b2)
        ln_kernel<8><<<NT, 128>>>(X, PART, b2 + (size_t)l * DD,
                                  ln2_g + (size_t)l * DD, ln2_b + (size_t)l * DD,
                                  X, x2);
    }

    // final LN -> fp16, tied LM head (fp16 single-pass, 128x128, GX=1)
    ln_kernel<0><<<NT, 128>>>(X, nullptr, nullptr, lnf_g, lnf_b,
                              nullptr, lnfh);
    gemm_mma<128,128,2,0,1><<<dim3(NT / 128, VV / 128), 256, SMEM_LM128>>>(
        lnfh, embh, nullptr, out, VV, DD, DD, 0);
}